// round 9
// baseline (speedup 1.0000x reference)
#include <cuda_runtime.h>
#include <cstdint>
#include <math.h>

#define IN_DIM 256
#define HIDDEN 64
#define MAX_NODES 100000
#define MAX_EDGES 1600000

// Scratch (allocation-free rule: __device__ globals). No float atomics, no inline PTX.
__device__ float g_h[MAX_NODES * HIDDEN];       // x @ W
__device__ float g_agg[MAX_NODES * HIDDEN];     // normalized aggregate
__device__ float g_dinv[MAX_NODES];             // deg^-1/2
__device__ int   g_degcnt[MAX_NODES];           // in-degree (edges only)
__device__ int   g_off[MAX_NODES + 1];          // CSR offsets (incoming)
__device__ int   g_cnt[MAX_NODES];              // bucket-fill cursors
__device__ int   g_csr_src[MAX_EDGES];          // src node per incoming edge
__device__ int   g_stride;                      // 1 = int32 edge_index, 2 = int64

// ---------------------------------------------------------------------------
// Dtype probe: JAX demotes jnp.int64 -> int32 unless x64 is enabled, so the
// edge buffer is most likely int32. For int64 (values < 2^31, little-endian)
// every odd 32-bit word is 0; for int32 data odd words are random node ids.
// ---------------------------------------------------------------------------
__global__ void detect_kernel(const int* __restrict__ ei) {
    if (threadIdx.x == 0 && blockIdx.x == 0) {
        int nz = 0;
        #pragma unroll
        for (int i = 1; i < 128; i += 2) nz |= ei[i];
        g_stride = (nz == 0) ? 2 : 1;    // all odd words zero -> int64 layout
    }
}

// ---------------------------------------------------------------------------
// Kernel 1: h = x @ W   (plain fp32 FMA, W-reuse tiling)
// Tile: 32 rows. Block: 128 threads = 16 col-quads x 8 row-slots.
// Each thread: 4 rows x 4 cols -> one 16B W load feeds 16 FMAs.
// ---------------------------------------------------------------------------
__global__ void gemm_kernel(const float* __restrict__ x, const float* __restrict__ W, int n) {
    __shared__ float xs[32][IN_DIM];          // 32 KB
    int row0 = blockIdx.x * 32;
    int valid = n - row0; if (valid > 32) valid = 32;

    if (valid == 32) {
        const float4* xg = reinterpret_cast<const float4*>(x + (size_t)row0 * IN_DIM);
        float4* xsv = reinterpret_cast<float4*>(&xs[0][0]);
        #pragma unroll
        for (int i = 0; i < 16; i++) xsv[threadIdx.x + i * 128] = xg[threadIdx.x + i * 128];
    } else {
        for (int idx = threadIdx.x; idx < 32 * IN_DIM; idx += 128) {
            int r = idx / IN_DIM, c = idx - r * IN_DIM;
            xs[r][c] = (r < valid) ? x[(size_t)(row0 + r) * IN_DIM + c] : 0.0f;
        }
    }
    __syncthreads();

    int rs   = threadIdx.x >> 4;          // 0..7  : row slot
    int col4 = (threadIdx.x & 15) * 4;    // 0,4,...,60

    float4 acc0 = make_float4(0.f, 0.f, 0.f, 0.f);
    float4 acc1 = acc0, acc2 = acc0, acc3 = acc0;
    const float* wp = W + col4;

    #pragma unroll 4
    for (int k = 0; k < IN_DIM; k++) {
        float4 wv = *reinterpret_cast<const float4*>(wp + k * HIDDEN);
        float x0 = xs[rs][k];
        float x1 = xs[rs +  8][k];
        float x2 = xs[rs + 16][k];
        float x3 = xs[rs + 24][k];
        acc0.x = fmaf(x0, wv.x, acc0.x); acc0.y = fmaf(x0, wv.y, acc0.y);
        acc0.z = fmaf(x0, wv.z, acc0.z); acc0.w = fmaf(x0, wv.w, acc0.w);
        acc1.x = fmaf(x1, wv.x, acc1.x); acc1.y = fmaf(x1, wv.y, acc1.y);
        acc1.z = fmaf(x1, wv.z, acc1.z); acc1.w = fmaf(x1, wv.w, acc1.w);
        acc2.x = fmaf(x2, wv.x, acc2.x); acc2.y = fmaf(x2, wv.y, acc2.y);
        acc2.z = fmaf(x2, wv.z, acc2.z); acc2.w = fmaf(x2, wv.w, acc2.w);
        acc3.x = fmaf(x3, wv.x, acc3.x); acc3.y = fmaf(x3, wv.y, acc3.y);
        acc3.z = fmaf(x3, wv.z, acc3.z); acc3.w = fmaf(x3, wv.w, acc3.w);
    }

    float* hb = g_h + (size_t)row0 * HIDDEN + col4;
    if (rs      < valid) *reinterpret_cast<float4*>(hb + (size_t)(rs     ) * HIDDEN) = acc0;
    if (rs +  8 < valid) *reinterpret_cast<float4*>(hb + (size_t)(rs +  8) * HIDDEN) = acc1;
    if (rs + 16 < valid) *reinterpret_cast<float4*>(hb + (size_t)(rs + 16) * HIDDEN) = acc2;
    if (rs + 24 < valid) *reinterpret_cast<float4*>(hb + (size_t)(rs + 24) * HIDDEN) = acc3;
}

// ---------------------------------------------------------------------------
// CSR build pipeline (int atomics only). Edge reads go through the stride.
// Element k of edge_index lives at 32-bit word k*stride (low word for int64).
// ---------------------------------------------------------------------------
__global__ void zero_counts_kernel(int n) {
    int i = blockIdx.x * blockDim.x + threadIdx.x;
    if (i < n) { g_degcnt[i] = 0; g_cnt[i] = 0; }
}

__global__ void deg_acc_kernel(const int* __restrict__ ei, int E) {
    int e = blockIdx.x * blockDim.x + threadIdx.x;
    if (e >= E) return;
    int st = g_stride;
    int d = ei[(size_t)st * (E + e)];              // dst element E+e
    atomicAdd(&g_degcnt[d], 1);
}

// Single-block chunked exclusive scan over g_degcnt -> g_off; also dinv.
__global__ void scan_kernel(int n) {
    const int T = 1024;
    __shared__ int s[T];
    int tid = threadIdx.x;
    int chunk = (n + T - 1) / T;
    int beg = tid * chunk;
    int end = beg + chunk; if (end > n) end = n;

    int sum = 0;
    for (int i = beg; i < end; i++) sum += g_degcnt[i];
    s[tid] = sum;
    __syncthreads();
    for (int o = 1; o < T; o <<= 1) {
        int v = (tid >= o) ? s[tid - o] : 0;
        __syncthreads();
        s[tid] += v;
        __syncthreads();
    }
    int base = s[tid] - sum;   // exclusive prefix for this chunk
    int run = base;
    for (int i = beg; i < end; i++) {
        int c = g_degcnt[i];
        g_off[i] = run;
        g_dinv[i] = rsqrtf((float)c + 1.0f);   // +1 self loop; always > 0
        run += c;
    }
    if (tid == T - 1) g_off[n] = run;
}

__global__ void bucket_fill_kernel(const int* __restrict__ ei, int E) {
    int e = blockIdx.x * blockDim.x + threadIdx.x;
    if (e >= E) return;
    int st = g_stride;
    int s = ei[(size_t)st * e];                    // src element e
    int d = ei[(size_t)st * (E + e)];              // dst element E+e
    int pos = g_off[d] + atomicAdd(&g_cnt[d], 1);
    g_csr_src[pos] = s;
}

// ---------------------------------------------------------------------------
// Gather: agg[d] = dinv[d]^2*h[d] + sum_{s in in(d)} dinv[s]*dinv[d]*h[s]
// 16 threads per node, float4 accumulator per thread. NO atomics.
// ---------------------------------------------------------------------------
__global__ void gather_kernel(int n) {
    int node = blockIdx.x * 16 + (threadIdx.x >> 4);
    int q = threadIdx.x & 15;
    if (node >= n) return;

    float dd = g_dinv[node];
    float4 hv0 = *reinterpret_cast<const float4*>(g_h + (size_t)node * HIDDEN + q * 4);
    float sl = dd * dd;
    float4 acc = make_float4(hv0.x * sl, hv0.y * sl, hv0.z * sl, hv0.w * sl);

    int beg = g_off[node];
    int end = g_off[node + 1];
    for (int j = beg; j < end; j++) {
        int s = g_csr_src[j];                         // broadcast within group
        float nrm = dd * g_dinv[s];
        float4 hv = *reinterpret_cast<const float4*>(g_h + (size_t)s * HIDDEN + q * 4);
        acc.x = fmaf(hv.x, nrm, acc.x);
        acc.y = fmaf(hv.y, nrm, acc.y);
        acc.z = fmaf(hv.z, nrm, acc.z);
        acc.w = fmaf(hv.w, nrm, acc.w);
    }
    *reinterpret_cast<float4*>(g_agg + (size_t)node * HIDDEN + q * 4) = acc;
}

// ---------------------------------------------------------------------------
// Output head: out[i] = sigmoid( (agg[i] + b) . w2 + b2 )  -- one warp/node
// ---------------------------------------------------------------------------
__global__ void out_kernel(const float* __restrict__ b, const float* __restrict__ w2,
                           const float* __restrict__ b2, float* __restrict__ out, int n) {
    int gtid = blockIdx.x * blockDim.x + threadIdx.x;
    int node = gtid >> 5;
    int lane = threadIdx.x & 31;
    if (node >= n) return;
    float2 a  = *reinterpret_cast<const float2*>(g_agg + (size_t)node * HIDDEN + lane * 2);
    float2 bb = *reinterpret_cast<const float2*>(b + lane * 2);
    float2 w  = *reinterpret_cast<const float2*>(w2 + lane * 2);
    float p = (a.x + bb.x) * w.x + (a.y + bb.y) * w.y;
    #pragma unroll
    for (int o = 16; o; o >>= 1) p += __shfl_xor_sync(0xffffffffu, p, o);
    if (lane == 0) {
        float z = p + b2[0];
        out[node] = 1.0f / (1.0f + __expf(-z));
    }
}

// ---------------------------------------------------------------------------
extern "C" void kernel_launch(void* const* d_in, const int* in_sizes, int n_in,
                              void* d_out, int out_size) {
    const float* x  = (const float*)d_in[0];
    const int*   ei = (const int*)d_in[1];      // int32 words (or int64 low/high pairs)
    const float* W  = (const float*)d_in[2];
    const float* b  = (const float*)d_in[3];
    const float* w2 = (const float*)d_in[4];
    const float* b2 = (const float*)d_in[5];
    float* out = (float*)d_out;

    int n = in_sizes[0] / IN_DIM;     // 100000
    int E = in_sizes[1] / 2;          // 1600000 (element count, dtype-independent)

    detect_kernel<<<1, 32>>>(ei);
    gemm_kernel<<<(n + 31) / 32, 128>>>(x, W, n);
    zero_counts_kernel<<<(n + 255) / 256, 256>>>(n);
    deg_acc_kernel<<<(E + 255) / 256, 256>>>(ei, E);
    scan_kernel<<<1, 1024>>>(n);
    bucket_fill_kernel<<<(E + 255) / 256, 256>>>(ei, E);
    gather_kernel<<<(n + 15) / 16, 256>>>(n);
    out_kernel<<<(n * 32 + 255) / 256, 256>>>(b, w2, b2, out, n);
}

// round 10
// speedup vs baseline: 5.6355x; 5.6355x over previous
#include <cuda_runtime.h>
#include <cstdint>
#include <math.h>

#define IN_DIM 256
#define HIDDEN 64
#define MAX_NODES 100000

// Scalar-collapsed pipeline state (allocation-free: __device__ globals)
__device__ float g_wv[IN_DIM];        // W @ w2  [256]
__device__ float g_cst;               // b.w2 + b2
__device__ float g_z[MAX_NODES];      // x @ wv
__device__ float g_zs[MAX_NODES];     // dinv * z
__device__ float g_dinv[MAX_NODES];   // (deg+1)^-1/2
__device__ float g_aggs[MAX_NODES];   // scalar aggregate (edge contributions)
__device__ int   g_degcnt[MAX_NODES];
__device__ int   g_stride;            // 1 = int32 edge_index, 2 = int64

// ---------------------------------------------------------------------------
// Dtype probe (JAX demotes int64->int32 unless x64 enabled; handle both).
// int64 little-endian with values < 2^31: every odd 32-bit word is 0.
// ---------------------------------------------------------------------------
__global__ void detect_kernel(const int* __restrict__ ei) {
    if (threadIdx.x == 0 && blockIdx.x == 0) {
        int nz = 0;
        #pragma unroll
        for (int i = 1; i < 128; i += 2) nz |= ei[i];
        g_stride = (nz == 0) ? 2 : 1;
    }
}

// ---------------------------------------------------------------------------
// Prep: wv = W @ w2 (256-vector), cst = b.w2 + b2.  One block, 256 threads.
// ---------------------------------------------------------------------------
__global__ void prep_kernel(const float* __restrict__ W, const float* __restrict__ b,
                            const float* __restrict__ w2, const float* __restrict__ b2) {
    int k = threadIdx.x;
    float s = 0.0f;
    #pragma unroll 8
    for (int j = 0; j < HIDDEN; j++) s = fmaf(W[k * HIDDEN + j], w2[j], s);
    g_wv[k] = s;
    if (k == 0) {
        float c = b2[0];
        for (int j = 0; j < HIDDEN; j++) c = fmaf(b[j], w2[j], c);
        g_cst = c;
    }
}

// ---------------------------------------------------------------------------
// z = x @ wv : one warp per row. Lane l loads x[row][4l..] and x[row][128+4l..]
// (2x float4, fully coalesced), dots with shared wv, warp-reduces.
// HBM-bound: 102 MB of x read once.
// ---------------------------------------------------------------------------
__global__ void z_kernel(const float* __restrict__ x, int n) {
    __shared__ float4 swv[IN_DIM / 4];
    if (threadIdx.x < IN_DIM / 4)
        swv[threadIdx.x] = reinterpret_cast<const float4*>(g_wv)[threadIdx.x];
    __syncthreads();

    int warp = (blockIdx.x * blockDim.x + threadIdx.x) >> 5;
    int lane = threadIdx.x & 31;
    if (warp >= n) return;

    const float4* xr = reinterpret_cast<const float4*>(x + (size_t)warp * IN_DIM);
    float4 a = xr[lane], c = xr[lane + 32];
    float4 w0 = swv[lane], w1 = swv[lane + 32];
    float p = a.x * w0.x + a.y * w0.y + a.z * w0.z + a.w * w0.w
            + c.x * w1.x + c.y * w1.y + c.z * w1.z + c.w * w1.w;
    #pragma unroll
    for (int o = 16; o; o >>= 1) p += __shfl_xor_sync(0xffffffffu, p, o);
    if (lane == 0) g_z[warp] = p;
}

// ---------------------------------------------------------------------------
__global__ void zero_kernel(int n) {
    int i = blockIdx.x * blockDim.x + threadIdx.x;
    if (i < n) { g_degcnt[i] = 0; g_aggs[i] = 0.0f; }
}

// In-degree histogram over dst row; 4 edges per thread, int4 loads when int32.
__global__ void deg_kernel(const int* __restrict__ ei, int E) {
    int t = blockIdx.x * blockDim.x + threadIdx.x;
    int e0 = t * 4;
    if (e0 >= E) return;
    int st = g_stride;
    if (st == 1 && e0 + 4 <= E) {
        int4 d4 = *reinterpret_cast<const int4*>(ei + E + e0);
        atomicAdd(&g_degcnt[d4.x], 1);
        atomicAdd(&g_degcnt[d4.y], 1);
        atomicAdd(&g_degcnt[d4.z], 1);
        atomicAdd(&g_degcnt[d4.w], 1);
    } else {
        int lim = (e0 + 4 < E) ? e0 + 4 : E;
        for (int e = e0; e < lim; e++)
            atomicAdd(&g_degcnt[ei[(size_t)st * (E + e)]], 1);
    }
}

// dinv = rsqrt(deg+1); zs = dinv * z
__global__ void dinv_kernel(int n) {
    int i = blockIdx.x * blockDim.x + threadIdx.x;
    if (i >= n) return;
    float dv = rsqrtf((float)g_degcnt[i] + 1.0f);
    g_dinv[i] = dv;
    g_zs[i] = dv * g_z[i];
}

// Edge scatter: aggs[d] += zs[s] * dinv[d]  (scalar fp32 RED — supported)
__global__ void scatter_kernel(const int* __restrict__ ei, int E) {
    int t = blockIdx.x * blockDim.x + threadIdx.x;
    int e0 = t * 4;
    if (e0 >= E) return;
    int st = g_stride;
    if (st == 1 && e0 + 4 <= E) {
        int4 s4 = *reinterpret_cast<const int4*>(ei + e0);
        int4 d4 = *reinterpret_cast<const int4*>(ei + E + e0);
        atomicAdd(&g_aggs[d4.x], g_zs[s4.x] * g_dinv[d4.x]);
        atomicAdd(&g_aggs[d4.y], g_zs[s4.y] * g_dinv[d4.y]);
        atomicAdd(&g_aggs[d4.z], g_zs[s4.z] * g_dinv[d4.z]);
        atomicAdd(&g_aggs[d4.w], g_zs[s4.w] * g_dinv[d4.w]);
    } else {
        int lim = (e0 + 4 < E) ? e0 + 4 : E;
        for (int e = e0; e < lim; e++) {
            int s = ei[(size_t)st * e];
            int d = ei[(size_t)st * (E + e)];
            atomicAdd(&g_aggs[d], g_zs[s] * g_dinv[d]);
        }
    }
}

// out[i] = sigmoid( aggs[i] + dinv[i]*zs[i] + cst )   (self-loop term folded in)
__global__ void out_kernel(float* __restrict__ out, int n) {
    int i = blockIdx.x * blockDim.x + threadIdx.x;
    if (i >= n) return;
    float zv = g_aggs[i] + g_dinv[i] * g_zs[i] + g_cst;
    out[i] = 1.0f / (1.0f + __expf(-zv));
}

// ---------------------------------------------------------------------------
extern "C" void kernel_launch(void* const* d_in, const int* in_sizes, int n_in,
                              void* d_out, int out_size) {
    const float* x  = (const float*)d_in[0];
    const int*   ei = (const int*)d_in[1];      // int32 words (or int64 pairs)
    const float* W  = (const float*)d_in[2];
    const float* b  = (const float*)d_in[3];
    const float* w2 = (const float*)d_in[4];
    const float* b2 = (const float*)d_in[5];
    float* out = (float*)d_out;

    int n = in_sizes[0] / IN_DIM;     // 100000
    int E = in_sizes[1] / 2;          // 1600000 elements per row

    int edge_blocks = (E / 4 + 255) / 256 + 1;

    detect_kernel<<<1, 32>>>(ei);
    prep_kernel<<<1, 256>>>(W, b, w2, b2);
    z_kernel<<<(n + 7) / 8, 256>>>(x, n);                 // 8 warps/block
    zero_kernel<<<(n + 255) / 256, 256>>>(n);
    deg_kernel<<<edge_blocks, 256>>>(ei, E);
    dinv_kernel<<<(n + 255) / 256, 256>>>(n);
    scatter_kernel<<<edge_blocks, 256>>>(ei, E);
    out_kernel<<<(n + 255) / 256, 256>>>(out, n);
}

// round 11
// speedup vs baseline: 5.6561x; 1.0037x over previous
#include <cuda_runtime.h>
#include <cstdint>
#include <math.h>

#define IN_DIM 256
#define HIDDEN 64
#define MAX_NODES 100000

// Scalar-collapsed pipeline state (allocation-free: __device__ globals)
__device__ float g_wv[IN_DIM];        // W @ w2  [256]
__device__ float g_cst;               // b.w2 + b2
__device__ float g_z[MAX_NODES];      // x @ wv
__device__ float g_zs[MAX_NODES];     // dinv * z
__device__ float g_dinv[MAX_NODES];   // (deg+1)^-1/2
__device__ float g_aggs[MAX_NODES];   // scalar aggregate (edge contributions)
__device__ int   g_degcnt[MAX_NODES];
__device__ int   g_stride;            // 1 = int32 edge_index, 2 = int64

// ---------------------------------------------------------------------------
// Fused init: dtype probe + wv = W@w2 + cst = b.w2 + b2.  One block.
// int64 little-endian with values < 2^31: every odd 32-bit word is 0.
// ---------------------------------------------------------------------------
__global__ void init_kernel(const int* __restrict__ ei, const float* __restrict__ W,
                            const float* __restrict__ b, const float* __restrict__ w2,
                            const float* __restrict__ b2) {
    int k = threadIdx.x;
    float s = 0.0f;
    #pragma unroll 8
    for (int j = 0; j < HIDDEN; j++) s = fmaf(W[k * HIDDEN + j], w2[j], s);
    g_wv[k] = s;
    if (k == 0) {
        float c = b2[0];
        for (int j = 0; j < HIDDEN; j++) c = fmaf(b[j], w2[j], c);
        g_cst = c;
        int nz = 0;
        #pragma unroll
        for (int i = 1; i < 128; i += 2) nz |= ei[i];
        g_stride = (nz == 0) ? 2 : 1;
    }
}

// ---------------------------------------------------------------------------
// z = x @ wv  (+ fused zeroing of degcnt/aggs).
// 512 threads = 16 warps/block, one warp per row; lane loads 2x float4
// (fully coalesced; 102 MB of x -> HBM-bound floor ~13 us).
// Each block also zeros its 16-element slice of degcnt/aggs.
// ---------------------------------------------------------------------------
__global__ void z_kernel(const float* __restrict__ x, int n) {
    __shared__ float4 swv[IN_DIM / 4];
    if (threadIdx.x < IN_DIM / 4)
        swv[threadIdx.x] = reinterpret_cast<const float4*>(g_wv)[threadIdx.x];

    // fused zero: block b clears elements [16b, 16b+16)
    int zi = blockIdx.x * 16 + (threadIdx.x & 15);
    if (threadIdx.x < 16 && zi < n) g_degcnt[zi] = 0;
    else if (threadIdx.x >= 16 && threadIdx.x < 32 && zi < n) g_aggs[zi] = 0.0f;
    __syncthreads();

    int row = blockIdx.x * 16 + (threadIdx.x >> 5);
    int lane = threadIdx.x & 31;
    if (row >= n) return;

    const float4* xr = reinterpret_cast<const float4*>(x + (size_t)row * IN_DIM);
    float4 a = xr[lane], c = xr[lane + 32];
    float4 w0 = swv[lane], w1 = swv[lane + 32];
    float p = a.x * w0.x + a.y * w0.y + a.z * w0.z + a.w * w0.w
            + c.x * w1.x + c.y * w1.y + c.z * w1.z + c.w * w1.w;
    #pragma unroll
    for (int o = 16; o; o >>= 1) p += __shfl_xor_sync(0xffffffffu, p, o);
    if (lane == 0) g_z[row] = p;
}

// ---------------------------------------------------------------------------
// In-degree histogram over dst row; 4 edges/thread, int4 loads when int32.
// ---------------------------------------------------------------------------
__global__ void deg_kernel(const int* __restrict__ ei, int E) {
    int t = blockIdx.x * blockDim.x + threadIdx.x;
    int e0 = t * 4;
    if (e0 >= E) return;
    int st = g_stride;
    if (st == 1 && e0 + 4 <= E) {
        int4 d4 = *reinterpret_cast<const int4*>(ei + E + e0);
        atomicAdd(&g_degcnt[d4.x], 1);
        atomicAdd(&g_degcnt[d4.y], 1);
        atomicAdd(&g_degcnt[d4.z], 1);
        atomicAdd(&g_degcnt[d4.w], 1);
    } else {
        int lim = (e0 + 4 < E) ? e0 + 4 : E;
        for (int e = e0; e < lim; e++)
            atomicAdd(&g_degcnt[ei[(size_t)st * (E + e)]], 1);
    }
}

// dinv = rsqrt(deg+1); zs = dinv * z
__global__ void dinv_kernel(int n) {
    int i = blockIdx.x * blockDim.x + threadIdx.x;
    if (i >= n) return;
    float dv = rsqrtf((float)g_degcnt[i] + 1.0f);
    g_dinv[i] = dv;
    g_zs[i] = dv * g_z[i];
}

// Edge scatter: aggs[d] += zs[s] * dinv[d]  (scalar fp32 RED)
__global__ void scatter_kernel(const int* __restrict__ ei, int E) {
    int t = blockIdx.x * blockDim.x + threadIdx.x;
    int e0 = t * 4;
    if (e0 >= E) return;
    int st = g_stride;
    if (st == 1 && e0 + 4 <= E) {
        int4 s4 = *reinterpret_cast<const int4*>(ei + e0);
        int4 d4 = *reinterpret_cast<const int4*>(ei + E + e0);
        atomicAdd(&g_aggs[d4.x], g_zs[s4.x] * g_dinv[d4.x]);
        atomicAdd(&g_aggs[d4.y], g_zs[s4.y] * g_dinv[d4.y]);
        atomicAdd(&g_aggs[d4.z], g_zs[s4.z] * g_dinv[d4.z]);
        atomicAdd(&g_aggs[d4.w], g_zs[s4.w] * g_dinv[d4.w]);
    } else {
        int lim = (e0 + 4 < E) ? e0 + 4 : E;
        for (int e = e0; e < lim; e++) {
            int s = ei[(size_t)st * e];
            int d = ei[(size_t)st * (E + e)];
            atomicAdd(&g_aggs[d], g_zs[s] * g_dinv[d]);
        }
    }
}

// out[i] = sigmoid( aggs[i] + dinv[i]*zs[i] + cst )
__global__ void out_kernel(float* __restrict__ out, int n) {
    int i = blockIdx.x * blockDim.x + threadIdx.x;
    if (i >= n) return;
    float zv = g_aggs[i] + g_dinv[i] * g_zs[i] + g_cst;
    out[i] = 1.0f / (1.0f + __expf(-zv));
}

// ---------------------------------------------------------------------------
extern "C" void kernel_launch(void* const* d_in, const int* in_sizes, int n_in,
                              void* d_out, int out_size) {
    const float* x  = (const float*)d_in[0];
    const int*   ei = (const int*)d_in[1];      // int32 words (or int64 pairs)
    const float* W  = (const float*)d_in[2];
    const float* b  = (const float*)d_in[3];
    const float* w2 = (const float*)d_in[4];
    const float* b2 = (const float*)d_in[5];
    float* out = (float*)d_out;

    int n = in_sizes[0] / IN_DIM;     // 100000
    int E = in_sizes[1] / 2;          // 1600000 elements per row

    int edge_blocks = (E / 4 + 255) / 256 + 1;

    init_kernel<<<1, 256>>>(ei, W, b, w2, b2);
    z_kernel<<<(n + 15) / 16, 512>>>(x, n);          // also zeros degcnt/aggs
    deg_kernel<<<edge_blocks, 256>>>(ei, E);
    dinv_kernel<<<(n + 255) / 256, 256>>>(n);
    scatter_kernel<<<edge_blocks, 256>>>(ei, E);
    out_kernel<<<(n + 255) / 256, 256>>>(out, n);
}